// round 10
// baseline (speedup 1.0000x reference)
#include <cuda_runtime.h>
#include <cuda_fp16.h>
#include <cstdint>

// new_M = M + phi^T V - (phi^T phi) M ; new_z = z + colsum(phi); phi = elu(K)+1
// K,V: (64, 8192, 128) fp32 flattened over (b,h).
// Phase1: fused fp16 mma.sync. Warps 0-7: G = phi^T phi, f32-accumulate,
//   symmetric band tiling. Warps 8-15: A = phi^T V, FP16-ACCUMULATE (A's
//   error budget is ~1e-3 of output scale; fp16 acc adds only ~2e-5).
// Phase2: reduce partials, new_M = M + A - G*M, new_z.

#define SS 8192
#define NBH 64
#define NS 2                 // S-splits per bh
#define SR (SS / NS)         // 4096
#define KC 32                // s per staged chunk
#define NCH (SR / KC)        // 128

__device__ float g_G[(size_t)NBH * NS * 16384];
__device__ float g_A[(size_t)NBH * NS * 16384];
__device__ float g_z[(size_t)NBH * NS * 8 * 128];

typedef unsigned long long u64;

// ---------------- helpers ----------------
__device__ __forceinline__ uint32_t smem_u32(const void* p) {
    uint32_t a;
    asm("{ .reg .u64 t; cvta.to.shared.u64 t, %1; cvt.u32.u64 %0, t; }"
        : "=r"(a) : "l"(p));
    return a;
}
__device__ __forceinline__ void ldsm4(uint32_t* r, uint32_t a) {
    asm volatile("ldmatrix.sync.aligned.m8n8.x4.shared.b16 {%0,%1,%2,%3}, [%4];"
                 : "=r"(r[0]), "=r"(r[1]), "=r"(r[2]), "=r"(r[3]) : "r"(a));
}
// f32-accumulate mma (C/D bits live in u32 regs)
__device__ __forceinline__ void mma16816f(uint32_t* c, const uint32_t* a,
                                          uint32_t b0, uint32_t b1) {
    asm volatile(
        "mma.sync.aligned.m16n8k16.row.col.f32.f16.f16.f32 "
        "{%0,%1,%2,%3}, {%4,%5,%6,%7}, {%8,%9}, {%0,%1,%2,%3};"
        : "+r"(c[0]), "+r"(c[1]), "+r"(c[2]), "+r"(c[3])
        : "r"(a[0]), "r"(a[1]), "r"(a[2]), "r"(a[3]), "r"(b0), "r"(b1));
}
// fp16-accumulate mma (D/C are 2x f16x2 regs)
__device__ __forceinline__ void mma16816h(uint32_t* c, const uint32_t* a,
                                          uint32_t b0, uint32_t b1) {
    asm volatile(
        "mma.sync.aligned.m16n8k16.row.col.f16.f16.f16.f16 "
        "{%0,%1}, {%2,%3,%4,%5}, {%6,%7}, {%0,%1};"
        : "+r"(c[0]), "+r"(c[1])
        : "r"(a[0]), "r"(a[1]), "r"(a[2]), "r"(a[3]), "r"(b0), "r"(b1));
}
__device__ __forceinline__ float phi_f(float x) {
    return x > 0.f ? x + 1.f : __expf(x);
}
__device__ __forceinline__ uint32_t packh2(float s1, float s0) {
    uint32_t r;  // low half <- s0, high half <- s1
    asm("cvt.rn.f16x2.f32 %0, %1, %2;" : "=r"(r) : "f"(s1), "f"(s0));
    return r;
}
// u32 index in an 8KB [d(128)][sq(16)] tile, XOR-swizzled on 16B groups
__device__ __forceinline__ int stoff(int d, int sq) {
    return (d << 4) + ((((sq >> 2) ^ ((d >> 1) & 3))) << 2) + (sq & 3);
}
// byte address for a 16B row-fragment: row d, 16B-group g
__device__ __forceinline__ uint32_t frag_addr(uint32_t base, int d, int g) {
    return base + (d << 6) + (((g ^ ((d >> 1) & 3))) << 4);
}

// ---------------------------------------------------------------------------
// Phase 1. grid (NS, NBH), 512 threads.
// ---------------------------------------------------------------------------
__global__ __launch_bounds__(512, 1)
void drp1_kernel(const float* __restrict__ K, const float* __restrict__ V) {
    __shared__ uint32_t smA[2][2048];   // phi fp16x2 [d][sq] swizzled
    __shared__ uint32_t smB[2][2048];   // V   fp16x2 [d][sq] swizzled

    const int split = blockIdx.x, bh = blockIdx.y;
    const int tid = threadIdx.x, w = tid >> 5, l = tid & 31;
    const int tg = w >> 3, w8 = w & 7;
    // A warps (tg=1): 64x32 tile
    const int mb = (w8 & 1) * 64, nb = (w8 >> 1) * 32;
    // G warps (tg=0): band b, SMSP-balanced pairing (b, 7-b)
    const int band = (w8 < 4) ? w8 : 11 - w8;
    const int rbase = band * 16;
    const int ntlo = 2 * band;
    const int d2 = tid & 63;          // d-pair owner (staging)
    const int sq0 = tid >> 6;         // 0..7

    const uint32_t baseA0 = smem_u32(smA), baseB0 = smem_u32(smB);
    const float* Kb = K + ((size_t)bh * SS + (size_t)split * SR) * 128;
    const float* Vb = V + ((size_t)bh * SS + (size_t)split * SR) * 128;

    // G warps: accs[nt*4+q] = f32 bits. A warps: accs[tile*2+j] = f16x2.
    uint32_t accs[64];
    #pragma unroll
    for (int i = 0; i < 64; i++) accs[i] = 0u;
    float z0 = 0.f, z1 = 0.f;

    float2 kp[4], vp[4];

    // ---- load chunk 0 ----
    #pragma unroll
    for (int j = 0; j < 2; j++) {
        const float* kr = Kb + (size_t)((sq0 + 8 * j) << 1) * 128 + 2 * d2;
        const float* vr = Vb + (size_t)((sq0 + 8 * j) << 1) * 128 + 2 * d2;
        kp[2 * j] = __ldg((const float2*)kr);
        kp[2 * j + 1] = __ldg((const float2*)(kr + 128));
        vp[2 * j] = __ldg((const float2*)vr);
        vp[2 * j + 1] = __ldg((const float2*)(vr + 128));
    }
    // ---- convert + store chunk 0 into buf 0 ----
    #pragma unroll
    for (int j = 0; j < 2; j++) {
        const int sq = sq0 + 8 * j;
        float p00 = phi_f(kp[2 * j].x),     p01 = phi_f(kp[2 * j].y);
        float p10 = phi_f(kp[2 * j + 1].x), p11 = phi_f(kp[2 * j + 1].y);
        smA[0][stoff(2 * d2, sq)]     = packh2(p10, p00);
        smA[0][stoff(2 * d2 + 1, sq)] = packh2(p11, p01);
        z0 += p00 + p10;
        z1 += p01 + p11;
        smB[0][stoff(2 * d2, sq)]     = packh2(vp[2 * j + 1].x, vp[2 * j].x);
        smB[0][stoff(2 * d2 + 1, sq)] = packh2(vp[2 * j + 1].y, vp[2 * j].y);
    }
    __syncthreads();

    for (int c = 0; c < NCH; c++) {
        const int buf = c & 1, nbuf = buf ^ 1;
        const bool has_next = (c + 1 < NCH);

        // ---- prefetch chunk c+1 ----
        if (has_next) {
            const float* Kc = Kb + (size_t)(c + 1) * KC * 128;
            const float* Vc = Vb + (size_t)(c + 1) * KC * 128;
            #pragma unroll
            for (int j = 0; j < 2; j++) {
                const float* kr = Kc + (size_t)((sq0 + 8 * j) << 1) * 128 + 2 * d2;
                const float* vr = Vc + (size_t)((sq0 + 8 * j) << 1) * 128 + 2 * d2;
                kp[2 * j] = __ldg((const float2*)kr);
                kp[2 * j + 1] = __ldg((const float2*)(kr + 128));
                vp[2 * j] = __ldg((const float2*)vr);
                vp[2 * j + 1] = __ldg((const float2*)(vr + 128));
            }
        }

        // ---- mma on buf ----
        {
            const uint32_t bA = baseA0 + (uint32_t)buf * 8192;
            if (tg == 0) {
                // G band warp: rows [rbase,rbase+16), cols [16*band,128), f32 acc
                #pragma unroll
                for (int ks = 0; ks < 2; ks++) {
                    const int g = 2 * ks + (l >> 4);
                    uint32_t af[4];
                    ldsm4(af, frag_addr(bA, rbase + (l & 15), g));
                    #pragma unroll
                    for (int p = 0; p < 8; p++) {
                        if (p >= band) {
                            uint32_t bb[4];
                            ldsm4(bb, frag_addr(bA, 16 * p + (l & 15), g));
                            mma16816f(&accs[(2 * p) * 4],     af, bb[0], bb[2]);
                            mma16816f(&accs[(2 * p + 1) * 4], af, bb[1], bb[3]);
                        }
                    }
                }
            } else {
                // A warp: 64x32 tile, fp16 accumulate
                const uint32_t bOp = baseB0 + (uint32_t)buf * 8192;
                #pragma unroll
                for (int ks = 0; ks < 2; ks++) {
                    const int g = 2 * ks + (l >> 4);
                    uint32_t af[4][4];
                    #pragma unroll
                    for (int mt = 0; mt < 4; mt++)
                        ldsm4(af[mt], frag_addr(bA, mb + 16 * mt + (l & 15), g));
                    uint32_t bb[2][4];
                    #pragma unroll
                    for (int p = 0; p < 2; p++)
                        ldsm4(bb[p], frag_addr(bOp, nb + 16 * p + (l & 15), g));
                    #pragma unroll
                    for (int mt = 0; mt < 4; mt++)
                        #pragma unroll
                        for (int nt = 0; nt < 4; nt++)
                            mma16816h(&accs[(mt * 4 + nt) * 2], af[mt],
                                      bb[nt >> 1][nt & 1], bb[nt >> 1][2 + (nt & 1)]);
                }
            }
        }

        // ---- convert + store chunk c+1 into nbuf ----
        if (has_next) {
            #pragma unroll
            for (int j = 0; j < 2; j++) {
                const int sq = sq0 + 8 * j;
                float p00 = phi_f(kp[2 * j].x),     p01 = phi_f(kp[2 * j].y);
                float p10 = phi_f(kp[2 * j + 1].x), p11 = phi_f(kp[2 * j + 1].y);
                smA[nbuf][stoff(2 * d2, sq)]     = packh2(p10, p00);
                smA[nbuf][stoff(2 * d2 + 1, sq)] = packh2(p11, p01);
                z0 += p00 + p10;
                z1 += p01 + p11;
                smB[nbuf][stoff(2 * d2, sq)]     = packh2(vp[2 * j + 1].x, vp[2 * j].x);
                smB[nbuf][stoff(2 * d2 + 1, sq)] = packh2(vp[2 * j + 1].y, vp[2 * j].y);
            }
        }
        __syncthreads();
    }

    // ---- epilogue ----
    const int r = l >> 2, cc = 2 * (l & 3);
    if (tg == 0) {
        float* dst = g_G + (size_t)(bh * NS + split) * 16384;
        const int row0 = rbase + r, row1 = rbase + r + 8;
        #pragma unroll
        for (int nt = 0; nt < 16; nt++) {
            if (nt >= ntlo) {
                const int col = 8 * nt + cc;
                float a0 = __uint_as_float(accs[nt * 4 + 0]);
                float a1 = __uint_as_float(accs[nt * 4 + 1]);
                float a2 = __uint_as_float(accs[nt * 4 + 2]);
                float a3 = __uint_as_float(accs[nt * 4 + 3]);
                *(float2*)(dst + (size_t)row0 * 128 + col) = make_float2(a0, a1);
                *(float2*)(dst + (size_t)row1 * 128 + col) = make_float2(a2, a3);
                if (nt >= ntlo + 2) {   // mirror strict-upper into lower
                    dst[(size_t)col * 128 + row0]       = a0;
                    dst[(size_t)(col + 1) * 128 + row0] = a1;
                    dst[(size_t)col * 128 + row1]       = a2;
                    dst[(size_t)(col + 1) * 128 + row1] = a3;
                }
            }
        }
    } else {
        float* dst = g_A + (size_t)(bh * NS + split) * 16384;
        #pragma unroll
        for (int mt = 0; mt < 4; mt++)
            #pragma unroll
            for (int nt = 0; nt < 4; nt++) {
                int row = mb + 16 * mt + r, col = nb + 8 * nt + cc;
                int tI = (mt * 4 + nt) * 2;
                float2 v0 = __half22float2(*(__half2*)&accs[tI]);
                float2 v1 = __half22float2(*(__half2*)&accs[tI + 1]);
                *(float2*)(dst + (size_t)row * 128 + col) = v0;
                *(float2*)(dst + (size_t)(row + 8) * 128 + col) = v1;
            }
    }

    // z partials
    *(float2*)(g_z + ((size_t)(bh * NS + split) * 8 + sq0) * 128 + 2 * d2) =
        make_float2(z0, z1);
}

// ---------------------------------------------------------------------------
// Phase 2: new_M = M + A - G*M ; new_z. grid (64, 4), 512 threads.
// ---------------------------------------------------------------------------
__device__ __forceinline__ u64 pk2(float x, float y) {
    u64 r; asm("mov.b64 %0,{%1,%2};" : "=l"(r) : "f"(x), "f"(y)); return r;
}
__device__ __forceinline__ void fma2(u64& c, u64 a, u64 b) {
    asm("fma.rn.f32x2 %0,%1,%2,%0;" : "+l"(c) : "l"(a), "l"(b));
}
__device__ __forceinline__ void add2(u64& c, u64 a) {
    asm("add.rn.f32x2 %0,%1,%0;" : "+l"(c) : "l"(a));
}

__global__ __launch_bounds__(512, 2)
void drp2_kernel(const float* __restrict__ M, const float* __restrict__ z,
                 float* __restrict__ out) {
    const int bh = blockIdx.x, q = blockIdx.y;
    __shared__ float GT[128 * 33];    // GT[i][kk], pad 33
    __shared__ float Msh[128 * 32];   // M[:, q*32 : q*32+32]

    const int tid = threadIdx.x;
    const int tx = tid & 7, ty = tid >> 3;    // 8 col-groups x 64 row-groups
    const int ra = ty * 2;                    // 2 rows
    const int cl = tx * 4;                    // local col (0..28)
    const int cb = q * 32 + cl;               // global col

    const float* Mp = M + (size_t)bh * 16384;
    const float* A0 = g_A + (size_t)bh * NS * 16384;
    const float* G0 = g_G + (size_t)bh * NS * 16384;

    // stage M slice
    for (int e = tid; e < 1024; e += 512) {
        int row = e >> 3, c4 = (e & 7) * 4;
        *(float4*)(Msh + row * 32 + c4) =
            __ldg((const float4*)(Mp + (size_t)row * 128 + q * 32 + c4));
    }
    __syncthreads();

    u64 acc[2][2];
    #pragma unroll
    for (int i = 0; i < 2; i++) {
        #pragma unroll
        for (int p = 0; p < 2; p++) {
            size_t o = (size_t)(ra + i) * 128 + cb + 2 * p;
            float2 m = *(const float2*)(Msh + (ra + i) * 32 + cl + 2 * p);
            u64 a = pk2(m.x, m.y);
            #pragma unroll
            for (int c = 0; c < NS; c++)
                add2(a, *(const u64*)(A0 + (size_t)c * 16384 + o));
            acc[i][p] = a;
        }
    }

    for (int ks = 0; ks < 128; ks += 32) {
        __syncthreads();
        for (int e = tid; e < 128 * 32; e += 512) {
            int kk = e & 31, i = e >> 5;
            float s = 0.f;
            #pragma unroll
            for (int c = 0; c < NS; c++)
                s += G0[(size_t)c * 16384 + (size_t)i * 128 + ks + kk];
            GT[i * 33 + kk] = s;
        }
        __syncthreads();

        #pragma unroll 8
        for (int kk = 0; kk < 32; kk++) {
            int k = ks + kk;
            float g0 = GT[(ra + 0) * 33 + kk];
            float g1 = GT[(ra + 1) * 33 + kk];
            float4 b = *(const float4*)(Msh + k * 32 + cl);
            u64 b0 = pk2(b.x, b.y), b1 = pk2(b.z, b.w);
            u64 pa0 = pk2(-g0, -g0), pa1 = pk2(-g1, -g1);
            fma2(acc[0][0], pa0, b0);
            fma2(acc[0][1], pa0, b1);
            fma2(acc[1][0], pa1, b0);
            fma2(acc[1][1], pa1, b1);
        }
    }

    float* outM = out + (size_t)bh * 16384;
    #pragma unroll
    for (int i = 0; i < 2; i++)
        #pragma unroll
        for (int p = 0; p < 2; p++)
            *(u64*)(outM + (size_t)(ra + i) * 128 + cb + 2 * p) = acc[i][p];

    if (q == 0 && tid < 128) {
        float s = z[(size_t)bh * 128 + tid];
        #pragma unroll
        for (int j = 0; j < NS * 8; j++)
            s += g_z[((size_t)bh * NS * 8 + j) * 128 + tid];
        out[(size_t)NBH * 16384 + (size_t)bh * 128 + tid] = s;
    }
}

extern "C" void kernel_launch(void* const* d_in, const int* in_sizes, int n_in,
                              void* d_out, int out_size) {
    const float* K = (const float*)d_in[0];
    const float* V = (const float*)d_in[1];
    const float* M = (const float*)d_in[2];
    const float* z = (const float*)d_in[3];
    float* out = (float*)d_out;

    drp1_kernel<<<dim3(NS, NBH), 512>>>(K, V);
    drp2_kernel<<<dim3(NBH, 4), 512>>>(M, z, out);
}

// round 11
// speedup vs baseline: 1.0295x; 1.0295x over previous
#include <cuda_runtime.h>
#include <cuda_fp16.h>
#include <cstdint>

// new_M = M + phi^T V - (phi^T phi) M ; new_z = z + colsum(phi); phi = elu(K)+1
// K,V: (64, 8192, 128) fp32 flattened over (b,h).
// Phase1: split CTAs, 2 per SM. G-CTA (tgt=0): G = phi^T phi, f32-acc,
//   symmetric band tiling, z sums. A-CTA (tgt=1): A = phi^T V, f32-acc.
//   Cross-CTA overlap hides staging/barrier overhead under the other CTA's MMAs.
// Phase2: reduce partials, new_M = M + A - G*M, new_z.

#define SS 8192
#define NBH 64
#define NS 2                 // S-splits per bh
#define SR (SS / NS)         // 4096
#define KC 32                // s per staged chunk
#define NCH (SR / KC)        // 128

__device__ float g_G[(size_t)NBH * NS * 16384];
__device__ float g_A[(size_t)NBH * NS * 16384];
__device__ float g_z[(size_t)NBH * NS * 4 * 128];

typedef unsigned long long u64;

// ---------------- helpers ----------------
__device__ __forceinline__ uint32_t smem_u32(const void* p) {
    uint32_t a;
    asm("{ .reg .u64 t; cvta.to.shared.u64 t, %1; cvt.u32.u64 %0, t; }"
        : "=r"(a) : "l"(p));
    return a;
}
__device__ __forceinline__ void ldsm4(uint32_t* r, uint32_t a) {
    asm volatile("ldmatrix.sync.aligned.m8n8.x4.shared.b16 {%0,%1,%2,%3}, [%4];"
                 : "=r"(r[0]), "=r"(r[1]), "=r"(r[2]), "=r"(r[3]) : "r"(a));
}
__device__ __forceinline__ void mma16816(float* c, const uint32_t* a,
                                         uint32_t b0, uint32_t b1) {
    asm volatile(
        "mma.sync.aligned.m16n8k16.row.col.f32.f16.f16.f32 "
        "{%0,%1,%2,%3}, {%4,%5,%6,%7}, {%8,%9}, {%0,%1,%2,%3};"
        : "+f"(c[0]), "+f"(c[1]), "+f"(c[2]), "+f"(c[3])
        : "r"(a[0]), "r"(a[1]), "r"(a[2]), "r"(a[3]), "r"(b0), "r"(b1));
}
__device__ __forceinline__ float phi_f(float x) {
    return x > 0.f ? x + 1.f : __expf(x);
}
__device__ __forceinline__ uint32_t packh2(float s1, float s0) {
    uint32_t r;  // low half <- s0, high half <- s1
    asm("cvt.rn.f16x2.f32 %0, %1, %2;" : "=r"(r) : "f"(s1), "f"(s0));
    return r;
}
// u32 index in an 8KB [d(128)][sq(16)] tile, XOR-swizzled on 16B groups
__device__ __forceinline__ int stoff(int d, int sq) {
    return (d << 4) + ((((sq >> 2) ^ ((d >> 1) & 3))) << 2) + (sq & 3);
}
// byte address for a 16B row-fragment: row d, 16B-group g
__device__ __forceinline__ uint32_t frag_addr(uint32_t base, int d, int g) {
    return base + (d << 6) + (((g ^ ((d >> 1) & 3))) << 4);
}

// ---------------------------------------------------------------------------
// Phase 1. grid (NS, NBH, 2), 256 threads, 2 CTAs/SM.
// ---------------------------------------------------------------------------
__global__ __launch_bounds__(256, 2)
void drp1_kernel(const float* __restrict__ K, const float* __restrict__ V) {
    __shared__ uint32_t smA[2][2048];   // phi fp16x2 [d][sq] swizzled
    __shared__ uint32_t smB[2][2048];   // V   fp16x2 (A-CTA only)

    const int split = blockIdx.x, bh = blockIdx.y, tgt = blockIdx.z;
    const int tid = threadIdx.x, w = tid >> 5, l = tid & 31;
    // G-CTA: band b on SMSP-balanced pairing (w, w+4) -> (b, 7-b)
    const int band = (w < 4) ? w : 11 - w;
    const int rbase = band * 16, ntlo = 2 * band;
    // A-CTA: 64x32 tile
    const int mb = (w & 1) * 64, nb = (w >> 1) * 32;
    const int d2 = tid & 63;          // d-pair owner (staging)
    const int sq0 = tid >> 6;         // 0..3

    const uint32_t baseA0 = smem_u32(smA), baseB0 = smem_u32(smB);
    const float* Kb = K + ((size_t)bh * SS + (size_t)split * SR) * 128;
    const float* Vb = V + ((size_t)bh * SS + (size_t)split * SR) * 128;

    float accs[16][4];
    #pragma unroll
    for (int i = 0; i < 16; i++)
        #pragma unroll
        for (int qq = 0; qq < 4; qq++) accs[i][qq] = 0.f;
    float z0 = 0.f, z1 = 0.f;

    float2 kp[8];

    // ---- chunk 0: load K, convert phi, (A) load V ----
    #pragma unroll
    for (int j = 0; j < 4; j++) {
        const float* kr = Kb + (size_t)((sq0 + 4 * j) << 1) * 128 + 2 * d2;
        kp[2 * j] = __ldg((const float2*)kr);
        kp[2 * j + 1] = __ldg((const float2*)(kr + 128));
    }
    #pragma unroll
    for (int j = 0; j < 4; j++) {
        const int sq = sq0 + 4 * j;
        float p00 = phi_f(kp[2 * j].x),     p01 = phi_f(kp[2 * j].y);
        float p10 = phi_f(kp[2 * j + 1].x), p11 = phi_f(kp[2 * j + 1].y);
        smA[0][stoff(2 * d2, sq)]     = packh2(p10, p00);
        smA[0][stoff(2 * d2 + 1, sq)] = packh2(p11, p01);
        if (tgt == 0) { z0 += p00 + p10; z1 += p01 + p11; }
    }
    if (tgt == 1) {
        #pragma unroll
        for (int j = 0; j < 4; j++) {
            const int sq = sq0 + 4 * j;
            const float* vr = Vb + (size_t)(sq << 1) * 128 + 2 * d2;
            float2 v0 = __ldg((const float2*)vr);
            float2 v1 = __ldg((const float2*)(vr + 128));
            smB[0][stoff(2 * d2, sq)]     = packh2(v1.x, v0.x);
            smB[0][stoff(2 * d2 + 1, sq)] = packh2(v1.y, v0.y);
        }
    }
    __syncthreads();

    for (int c = 0; c < NCH; c++) {
        const int buf = c & 1, nbuf = buf ^ 1;
        const bool has_next = (c + 1 < NCH);

        // ---- prefetch next K into regs (lands during MMA) ----
        if (has_next) {
            const float* Kc = Kb + (size_t)(c + 1) * KC * 128;
            #pragma unroll
            for (int j = 0; j < 4; j++) {
                const float* kr = Kc + (size_t)((sq0 + 4 * j) << 1) * 128 + 2 * d2;
                kp[2 * j] = __ldg((const float2*)kr);
                kp[2 * j + 1] = __ldg((const float2*)(kr + 128));
            }
        }

        // ---- mma on buf ----
        {
            const uint32_t bA = baseA0 + (uint32_t)buf * 8192;
            if (tgt == 0) {
                // G band warp: rows [rbase,rbase+16), cols [16*band,128)
                #pragma unroll
                for (int ks = 0; ks < 2; ks++) {
                    const int g = 2 * ks + (l >> 4);
                    uint32_t af[4];
                    ldsm4(af, frag_addr(bA, rbase + (l & 15), g));
                    #pragma unroll
                    for (int p = 0; p < 8; p++) {
                        if (p >= band) {
                            uint32_t bb[4];
                            ldsm4(bb, frag_addr(bA, 16 * p + (l & 15), g));
                            mma16816(accs[2 * p],     af, bb[0], bb[2]);
                            mma16816(accs[2 * p + 1], af, bb[1], bb[3]);
                        }
                    }
                }
            } else {
                // A warp: 64x32 tile
                const uint32_t bOp = baseB0 + (uint32_t)buf * 8192;
                #pragma unroll
                for (int ks = 0; ks < 2; ks++) {
                    const int g = 2 * ks + (l >> 4);
                    uint32_t af[4][4];
                    #pragma unroll
                    for (int mt = 0; mt < 4; mt++)
                        ldsm4(af[mt], frag_addr(bA, mb + 16 * mt + (l & 15), g));
                    uint32_t bb[2][4];
                    #pragma unroll
                    for (int p = 0; p < 2; p++)
                        ldsm4(bb[p], frag_addr(bOp, nb + 16 * p + (l & 15), g));
                    #pragma unroll
                    for (int mt = 0; mt < 4; mt++)
                        #pragma unroll
                        for (int nt = 0; nt < 4; nt++)
                            mma16816(accs[mt * 4 + nt], af[mt],
                                     bb[nt >> 1][nt & 1], bb[nt >> 1][2 + (nt & 1)]);
                }
            }
        }

        // ---- convert + store chunk c+1 into nbuf ----
        if (has_next) {
            #pragma unroll
            for (int j = 0; j < 4; j++) {
                const int sq = sq0 + 4 * j;
                float p00 = phi_f(kp[2 * j].x),     p01 = phi_f(kp[2 * j].y);
                float p10 = phi_f(kp[2 * j + 1].x), p11 = phi_f(kp[2 * j + 1].y);
                smA[nbuf][stoff(2 * d2, sq)]     = packh2(p10, p00);
                smA[nbuf][stoff(2 * d2 + 1, sq)] = packh2(p11, p01);
                if (tgt == 0) { z0 += p00 + p10; z1 += p01 + p11; }
            }
            if (tgt == 1) {
                const float* Vc = Vb + (size_t)(c + 1) * KC * 128;
                #pragma unroll
                for (int j = 0; j < 4; j++) {
                    const int sq = sq0 + 4 * j;
                    const float* vr = Vc + (size_t)(sq << 1) * 128 + 2 * d2;
                    float2 v0 = __ldg((const float2*)vr);
                    float2 v1 = __ldg((const float2*)(vr + 128));
                    smB[nbuf][stoff(2 * d2, sq)]     = packh2(v1.x, v0.x);
                    smB[nbuf][stoff(2 * d2 + 1, sq)] = packh2(v1.y, v0.y);
                }
            }
        }
        __syncthreads();
    }

    // ---- epilogue ----
    const int r = l >> 2, cc = 2 * (l & 3);
    if (tgt == 0) {
        float* dst = g_G + (size_t)(bh * NS + split) * 16384;
        const int row0 = rbase + r, row1 = rbase + r + 8;
        #pragma unroll
        for (int nt = 0; nt < 16; nt++) {
            if (nt >= ntlo) {
                const int col = 8 * nt + cc;
                *(float2*)(dst + (size_t)row0 * 128 + col) =
                    make_float2(accs[nt][0], accs[nt][1]);
                *(float2*)(dst + (size_t)row1 * 128 + col) =
                    make_float2(accs[nt][2], accs[nt][3]);
                if (nt >= ntlo + 2) {   // mirror strict-upper into lower
                    dst[(size_t)col * 128 + row0]       = accs[nt][0];
                    dst[(size_t)(col + 1) * 128 + row0] = accs[nt][1];
                    dst[(size_t)col * 128 + row1]       = accs[nt][2];
                    dst[(size_t)(col + 1) * 128 + row1] = accs[nt][3];
                }
            }
        }
        // z partials (unique (sq0, d2) slots)
        *(float2*)(g_z + ((size_t)(bh * NS + split) * 4 + sq0) * 128 + 2 * d2) =
            make_float2(z0, z1);
    } else {
        float* dst = g_A + (size_t)(bh * NS + split) * 16384;
        #pragma unroll
        for (int mt = 0; mt < 4; mt++)
            #pragma unroll
            for (int nt = 0; nt < 4; nt++) {
                int row = mb + 16 * mt + r, col = nb + 8 * nt + cc;
                *(float2*)(dst + (size_t)row * 128 + col) =
                    make_float2(accs[mt * 4 + nt][0], accs[mt * 4 + nt][1]);
                *(float2*)(dst + (size_t)(row + 8) * 128 + col) =
                    make_float2(accs[mt * 4 + nt][2], accs[mt * 4 + nt][3]);
            }
    }
}

// ---------------------------------------------------------------------------
// Phase 2: new_M = M + A - G*M ; new_z. grid (64, 4), 512 threads.
// ---------------------------------------------------------------------------
__device__ __forceinline__ u64 pk2(float x, float y) {
    u64 r; asm("mov.b64 %0,{%1,%2};" : "=l"(r) : "f"(x), "f"(y)); return r;
}
__device__ __forceinline__ void fma2(u64& c, u64 a, u64 b) {
    asm("fma.rn.f32x2 %0,%1,%2,%0;" : "+l"(c) : "l"(a), "l"(b));
}
__device__ __forceinline__ void add2(u64& c, u64 a) {
    asm("add.rn.f32x2 %0,%1,%0;" : "+l"(c) : "l"(a));
}

__global__ __launch_bounds__(512, 2)
void drp2_kernel(const float* __restrict__ M, const float* __restrict__ z,
                 float* __restrict__ out) {
    const int bh = blockIdx.x, q = blockIdx.y;
    __shared__ float GT[128 * 33];    // GT[i][kk], pad 33
    __shared__ float Msh[128 * 32];   // M[:, q*32 : q*32+32]

    const int tid = threadIdx.x;
    const int tx = tid & 7, ty = tid >> 3;    // 8 col-groups x 64 row-groups
    const int ra = ty * 2;                    // 2 rows
    const int cl = tx * 4;                    // local col (0..28)
    const int cb = q * 32 + cl;               // global col

    const float* Mp = M + (size_t)bh * 16384;
    const float* A0 = g_A + (size_t)bh * NS * 16384;
    const float* G0 = g_G + (size_t)bh * NS * 16384;

    // stage M slice
    for (int e = tid; e < 1024; e += 512) {
        int row = e >> 3, c4 = (e & 7) * 4;
        *(float4*)(Msh + row * 32 + c4) =
            __ldg((const float4*)(Mp + (size_t)row * 128 + q * 32 + c4));
    }
    __syncthreads();

    u64 acc[2][2];
    #pragma unroll
    for (int i = 0; i < 2; i++) {
        #pragma unroll
        for (int p = 0; p < 2; p++) {
            size_t o = (size_t)(ra + i) * 128 + cb + 2 * p;
            float2 m = *(const float2*)(Msh + (ra + i) * 32 + cl + 2 * p);
            u64 a = pk2(m.x, m.y);
            #pragma unroll
            for (int c = 0; c < NS; c++)
                add2(a, *(const u64*)(A0 + (size_t)c * 16384 + o));
            acc[i][p] = a;
        }
    }

    for (int ks = 0; ks < 128; ks += 32) {
        __syncthreads();
        for (int e = tid; e < 128 * 32; e += 512) {
            int kk = e & 31, i = e >> 5;
            float s = 0.f;
            #pragma unroll
            for (int c = 0; c < NS; c++)
                s += G0[(size_t)c * 16384 + (size_t)i * 128 + ks + kk];
            GT[i * 33 + kk] = s;
        }
        __syncthreads();

        #pragma unroll 8
        for (int kk = 0; kk < 32; kk++) {
            int k = ks + kk;
            float g0 = GT[(ra + 0) * 33 + kk];
            float g1 = GT[(ra + 1) * 33 + kk];
            float4 b = *(const float4*)(Msh + k * 32 + cl);
            u64 b0 = pk2(b.x, b.y), b1 = pk2(b.z, b.w);
            u64 pa0 = pk2(-g0, -g0), pa1 = pk2(-g1, -g1);
            fma2(acc[0][0], pa0, b0);
            fma2(acc[0][1], pa0, b1);
            fma2(acc[1][0], pa1, b0);
            fma2(acc[1][1], pa1, b1);
        }
    }

    float* outM = out + (size_t)bh * 16384;
    #pragma unroll
    for (int i = 0; i < 2; i++)
        #pragma unroll
        for (int p = 0; p < 2; p++)
            *(u64*)(outM + (size_t)(ra + i) * 128 + cb + 2 * p) = acc[i][p];

    if (q == 0 && tid < 128) {
        float s = z[(size_t)bh * 128 + tid];
        #pragma unroll
        for (int j = 0; j < NS * 4; j++)
            s += g_z[((size_t)bh * NS * 4 + j) * 128 + tid];
        out[(size_t)NBH * 16384 + (size_t)bh * 128 + tid] = s;
    }
}

extern "C" void kernel_launch(void* const* d_in, const int* in_sizes, int n_in,
                              void* d_out, int out_size) {
    const float* K = (const float*)d_in[0];
    const float* V = (const float*)d_in[1];
    const float* M = (const float*)d_in[2];
    const float* z = (const float*)d_in[3];
    float* out = (float*)d_out;

    drp1_kernel<<<dim3(NS, NBH, 2), 256>>>(K, V);
    drp2_kernel<<<dim3(NBH, 4), 512>>>(M, z, out);
}

// round 12
// speedup vs baseline: 1.4885x; 1.4458x over previous
#include <cuda_runtime.h>
#include <cuda_fp16.h>
#include <cstdint>

// new_M = M + phi^T V - (phi^T phi) M ; new_z = z + colsum(phi); phi = elu(K)+1
// K,V: (64, 8192, 128) fp32 flattened over (b,h) -> contiguous (524288, 128).
// Phase1: persistent balanced mapping: 148 CTAs, each owns ~110 global
//   32-row chunks (chunk ch -> bh = ch>>8). Fused fp16 mma.sync CTA:
//   warps 0-7 G = phi^T phi (symmetric band tiling), warps 8-15 A = phi^T V.
//   On bh-boundary / end, flush partial G/A/z to per-(cta,seg) scratch.
// Phase2: per bh, enumerate contributing (cta,seg) slots arithmetically,
//   reduce, new_M = M + A - G*M, new_z.

#define NBH 64
#define NCTA 148
#define TOTCH 16384          // 64 bh * 256 chunks of 32 rows

__device__ float g_Gs[(size_t)NCTA * 2 * 16384];
__device__ float g_As[(size_t)NCTA * 2 * 16384];
__device__ float g_zs[(size_t)NCTA * 2 * 1024];

typedef unsigned long long u64;

// ---------------- helpers ----------------
__device__ __forceinline__ uint32_t smem_u32(const void* p) {
    uint32_t a;
    asm("{ .reg .u64 t; cvta.to.shared.u64 t, %1; cvt.u32.u64 %0, t; }"
        : "=r"(a) : "l"(p));
    return a;
}
__device__ __forceinline__ void ldsm4(uint32_t* r, uint32_t a) {
    asm volatile("ldmatrix.sync.aligned.m8n8.x4.shared.b16 {%0,%1,%2,%3}, [%4];"
                 : "=r"(r[0]), "=r"(r[1]), "=r"(r[2]), "=r"(r[3]) : "r"(a));
}
__device__ __forceinline__ void mma16816(float* c, const uint32_t* a,
                                         uint32_t b0, uint32_t b1) {
    asm volatile(
        "mma.sync.aligned.m16n8k16.row.col.f32.f16.f16.f32 "
        "{%0,%1,%2,%3}, {%4,%5,%6,%7}, {%8,%9}, {%0,%1,%2,%3};"
        : "+f"(c[0]), "+f"(c[1]), "+f"(c[2]), "+f"(c[3])
        : "r"(a[0]), "r"(a[1]), "r"(a[2]), "r"(a[3]), "r"(b0), "r"(b1));
}
__device__ __forceinline__ float phi_f(float x) {
    return x > 0.f ? x + 1.f : __expf(x);
}
__device__ __forceinline__ uint32_t packh2(float s1, float s0) {
    uint32_t r;  // low half <- s0, high half <- s1
    asm("cvt.rn.f16x2.f32 %0, %1, %2;" : "=r"(r) : "f"(s1), "f"(s0));
    return r;
}
// u32 index in an 8KB [d(128)][sq(16)] tile, XOR-swizzled on 16B groups
__device__ __forceinline__ int stoff(int d, int sq) {
    return (d << 4) + ((((sq >> 2) ^ ((d >> 1) & 3))) << 2) + (sq & 3);
}
// byte address for a 16B row-fragment: row d, 16B-group g
__device__ __forceinline__ uint32_t frag_addr(uint32_t base, int d, int g) {
    return base + (d << 6) + (((g ^ ((d >> 1) & 3))) << 4);
}

// ---------------------------------------------------------------------------
// Phase 1. grid NCTA, 512 threads, persistent balanced chunks.
// ---------------------------------------------------------------------------
__global__ __launch_bounds__(512, 1)
void drp1_kernel(const float* __restrict__ K, const float* __restrict__ V) {
    __shared__ uint32_t smA[2][2048];   // phi fp16x2 [d][sq] swizzled
    __shared__ uint32_t smB[2][2048];   // V   fp16x2 [d][sq] swizzled

    const int cta = blockIdx.x;
    const int start = (cta * TOTCH) / NCTA;
    const int end   = ((cta + 1) * TOTCH) / NCTA;

    const int tid = threadIdx.x, w = tid >> 5, l = tid & 31;
    const int tg = w >> 3, w8 = w & 7;
    const int mb = (w8 & 1) * 64, nb = (w8 >> 1) * 32;      // A warps
    const int band = (w8 < 4) ? w8 : 11 - w8;               // G warps
    const int rbase = band * 16, ntlo = 2 * band;
    const int d2 = tid & 63;          // d-pair owner (staging)
    const int sq0 = tid >> 6;         // 0..7
    const int r = l >> 2, cc = 2 * (l & 3);

    const uint32_t baseA0 = smem_u32(smA), baseB0 = smem_u32(smB);

    float accs[16][4];
    #pragma unroll
    for (int i = 0; i < 16; i++)
        #pragma unroll
        for (int qq = 0; qq < 4; qq++) accs[i][qq] = 0.f;
    float z0 = 0.f, z1 = 0.f;
    int seg = 0;
    int b1 = ((start >> 8) + 1) << 8;   // next bh boundary chunk

    float2 kp[4], vp[4];

    // ---- prologue: load + convert chunk `start` into buf 0 ----
    {
        const float* Kc = K + (size_t)start * 4096;
        const float* Vc = V + (size_t)start * 4096;
        #pragma unroll
        for (int j = 0; j < 2; j++) {
            const float* kr = Kc + (size_t)((sq0 + 8 * j) << 1) * 128 + 2 * d2;
            const float* vr = Vc + (size_t)((sq0 + 8 * j) << 1) * 128 + 2 * d2;
            kp[2 * j] = __ldg((const float2*)kr);
            kp[2 * j + 1] = __ldg((const float2*)(kr + 128));
            vp[2 * j] = __ldg((const float2*)vr);
            vp[2 * j + 1] = __ldg((const float2*)(vr + 128));
        }
        #pragma unroll
        for (int j = 0; j < 2; j++) {
            const int sq = sq0 + 8 * j;
            float p00 = phi_f(kp[2 * j].x),     p01 = phi_f(kp[2 * j].y);
            float p10 = phi_f(kp[2 * j + 1].x), p11 = phi_f(kp[2 * j + 1].y);
            smA[0][stoff(2 * d2, sq)]     = packh2(p10, p00);
            smA[0][stoff(2 * d2 + 1, sq)] = packh2(p11, p01);
            z0 += p00 + p10;
            z1 += p01 + p11;
            smB[0][stoff(2 * d2, sq)]     = packh2(vp[2 * j + 1].x, vp[2 * j].x);
            smB[0][stoff(2 * d2 + 1, sq)] = packh2(vp[2 * j + 1].y, vp[2 * j].y);
        }
    }
    __syncthreads();

    for (int ch = start; ch < end; ch++) {
        const int buf = (ch - start) & 1, nbuf = buf ^ 1;
        const bool has_next = (ch + 1 < end);

        // ---- prefetch chunk ch+1 ----
        if (has_next) {
            const float* Kc = K + (size_t)(ch + 1) * 4096;
            const float* Vc = V + (size_t)(ch + 1) * 4096;
            #pragma unroll
            for (int j = 0; j < 2; j++) {
                const float* kr = Kc + (size_t)((sq0 + 8 * j) << 1) * 128 + 2 * d2;
                const float* vr = Vc + (size_t)((sq0 + 8 * j) << 1) * 128 + 2 * d2;
                kp[2 * j] = __ldg((const float2*)kr);
                kp[2 * j + 1] = __ldg((const float2*)(kr + 128));
                vp[2 * j] = __ldg((const float2*)vr);
                vp[2 * j + 1] = __ldg((const float2*)(vr + 128));
            }
        }

        // ---- mma on buf ----
        {
            const uint32_t bA = baseA0 + (uint32_t)buf * 8192;
            if (tg == 0) {
                // G band warp: rows [rbase,rbase+16), cols [16*band,128)
                #pragma unroll
                for (int ks = 0; ks < 2; ks++) {
                    const int g = 2 * ks + (l >> 4);
                    uint32_t af[4];
                    ldsm4(af, frag_addr(bA, rbase + (l & 15), g));
                    #pragma unroll
                    for (int p = 0; p < 8; p++) {
                        if (p >= band) {
                            uint32_t bb[4];
                            ldsm4(bb, frag_addr(bA, 16 * p + (l & 15), g));
                            mma16816(accs[2 * p],     af, bb[0], bb[2]);
                            mma16816(accs[2 * p + 1], af, bb[1], bb[3]);
                        }
                    }
                }
            } else {
                // A warp: 64x32 tile
                const uint32_t bOp = baseB0 + (uint32_t)buf * 8192;
                #pragma unroll
                for (int ks = 0; ks < 2; ks++) {
                    const int g = 2 * ks + (l >> 4);
                    uint32_t af[4][4];
                    #pragma unroll
                    for (int mt = 0; mt < 4; mt++)
                        ldsm4(af[mt], frag_addr(bA, mb + 16 * mt + (l & 15), g));
                    uint32_t bb[2][4];
                    #pragma unroll
                    for (int p = 0; p < 2; p++)
                        ldsm4(bb[p], frag_addr(bOp, nb + 16 * p + (l & 15), g));
                    #pragma unroll
                    for (int mt = 0; mt < 4; mt++)
                        #pragma unroll
                        for (int nt = 0; nt < 4; nt++)
                            mma16816(accs[mt * 4 + nt], af[mt],
                                     bb[nt >> 1][nt & 1], bb[nt >> 1][2 + (nt & 1)]);
                }
            }
        }

        // ---- segment flush (bh boundary or end of range) ----
        if (ch + 1 == b1 || ch + 1 == end) {
            const int slot = cta * 2 + seg;
            if (tg == 0) {
                float* dst = g_Gs + (size_t)slot * 16384;
                const int row0 = rbase + r, row1 = rbase + r + 8;
                #pragma unroll
                for (int nt = 0; nt < 16; nt++) {
                    if (nt >= ntlo) {
                        const int col = 8 * nt + cc;
                        *(float2*)(dst + (size_t)row0 * 128 + col) =
                            make_float2(accs[nt][0], accs[nt][1]);
                        *(float2*)(dst + (size_t)row1 * 128 + col) =
                            make_float2(accs[nt][2], accs[nt][3]);
                        if (nt >= ntlo + 2) {   // mirror strict-upper into lower
                            dst[(size_t)col * 128 + row0]       = accs[nt][0];
                            dst[(size_t)(col + 1) * 128 + row0] = accs[nt][1];
                            dst[(size_t)col * 128 + row1]       = accs[nt][2];
                            dst[(size_t)(col + 1) * 128 + row1] = accs[nt][3];
                        }
                    }
                }
            } else {
                float* dst = g_As + (size_t)slot * 16384;
                #pragma unroll
                for (int mt = 0; mt < 4; mt++)
                    #pragma unroll
                    for (int nt = 0; nt < 4; nt++) {
                        int row = mb + 16 * mt + r, col = nb + 8 * nt + cc;
                        *(float2*)(dst + (size_t)row * 128 + col) =
                            make_float2(accs[mt * 4 + nt][0], accs[mt * 4 + nt][1]);
                        *(float2*)(dst + (size_t)(row + 8) * 128 + col) =
                            make_float2(accs[mt * 4 + nt][2], accs[mt * 4 + nt][3]);
                    }
            }
            // z (all 512 threads own unique (sq0, d2) slots)
            *(float2*)(g_zs + (size_t)slot * 1024 + sq0 * 128 + 2 * d2) =
                make_float2(z0, z1);

            seg = 1; b1 = 1 << 30;
            #pragma unroll
            for (int i = 0; i < 16; i++)
                #pragma unroll
                for (int qq = 0; qq < 4; qq++) accs[i][qq] = 0.f;
            z0 = z1 = 0.f;
        }

        // ---- convert + store chunk ch+1 into nbuf ----
        if (has_next) {
            #pragma unroll
            for (int j = 0; j < 2; j++) {
                const int sq = sq0 + 8 * j;
                float p00 = phi_f(kp[2 * j].x),     p01 = phi_f(kp[2 * j].y);
                float p10 = phi_f(kp[2 * j + 1].x), p11 = phi_f(kp[2 * j + 1].y);
                smA[nbuf][stoff(2 * d2, sq)]     = packh2(p10, p00);
                smA[nbuf][stoff(2 * d2 + 1, sq)] = packh2(p11, p01);
                z0 += p00 + p10;
                z1 += p01 + p11;
                smB[nbuf][stoff(2 * d2, sq)]     = packh2(vp[2 * j + 1].x, vp[2 * j].x);
                smB[nbuf][stoff(2 * d2 + 1, sq)] = packh2(vp[2 * j + 1].y, vp[2 * j].y);
            }
        }
        __syncthreads();
    }
}

// ---------------------------------------------------------------------------
// Phase 2: new_M = M + A - G*M ; new_z. grid (64, 4), 512 threads.
// ---------------------------------------------------------------------------
__device__ __forceinline__ u64 pk2(float x, float y) {
    u64 r; asm("mov.b64 %0,{%1,%2};" : "=l"(r) : "f"(x), "f"(y)); return r;
}
__device__ __forceinline__ void fma2(u64& c, u64 a, u64 b) {
    asm("fma.rn.f32x2 %0,%1,%2,%0;" : "+l"(c) : "l"(a), "l"(b));
}
__device__ __forceinline__ void add2(u64& c, u64 a) {
    asm("add.rn.f32x2 %0,%1,%0;" : "+l"(c) : "l"(a));
}

__global__ __launch_bounds__(512, 2)
void drp2_kernel(const float* __restrict__ M, const float* __restrict__ z,
                 float* __restrict__ out) {
    const int bh = blockIdx.x, q = blockIdx.y;
    __shared__ float GT[128 * 33];    // GT[i][kk], pad 33
    __shared__ float Msh[128 * 32];   // M[:, q*32 : q*32+32]
    __shared__ int s_cnt, s_slot[6];

    const int tid = threadIdx.x;
    const int tx = tid & 7, ty = tid >> 3;    // 8 col-groups x 64 row-groups
    const int ra = ty * 2;                    // 2 rows
    const int cl = tx * 4;                    // local col (0..28)
    const int cb = q * 32 + cl;               // global col

    const float* Mp = M + (size_t)bh * 16384;

    // enumerate contributing (cta, seg) scratch slots for this bh
    if (tid == 0) {
        const int lo = bh << 8, hi = lo + 256;
        int cnt = 0;
        int i0 = (lo * NCTA) / TOTCH;
        if (i0 > 0) i0--;
        for (int i = i0; i < NCTA && cnt < 6; i++) {
            int s = (i * TOTCH) / NCTA;
            if (s >= hi) break;
            int e = ((i + 1) * TOTCH) / NCTA;
            if (e > lo) {
                int sg = ((s >> 8) == bh) ? 0 : 1;
                s_slot[cnt++] = i * 2 + sg;
            }
        }
        s_cnt = cnt;
    }

    // stage M slice
    for (int e = tid; e < 1024; e += 512) {
        int row = e >> 3, c4 = (e & 7) * 4;
        *(float4*)(Msh + row * 32 + c4) =
            __ldg((const float4*)(Mp + (size_t)row * 128 + q * 32 + c4));
    }
    __syncthreads();

    const int ns = s_cnt;

    u64 acc[2][2];
    #pragma unroll
    for (int i = 0; i < 2; i++) {
        #pragma unroll
        for (int p = 0; p < 2; p++) {
            size_t o = (size_t)(ra + i) * 128 + cb + 2 * p;
            float2 m = *(const float2*)(Msh + (ra + i) * 32 + cl + 2 * p);
            u64 a = pk2(m.x, m.y);
            for (int s = 0; s < ns; s++)
                add2(a, *(const u64*)(g_As + (size_t)s_slot[s] * 16384 + o));
            acc[i][p] = a;
        }
    }

    for (int ks = 0; ks < 128; ks += 32) {
        __syncthreads();
        for (int e = tid; e < 128 * 32; e += 512) {
            int kk = e & 31, i = e >> 5;
            float s = 0.f;
            for (int c = 0; c < ns; c++)
                s += g_Gs[(size_t)s_slot[c] * 16384 + (size_t)i * 128 + ks + kk];
            GT[i * 33 + kk] = s;
        }
        __syncthreads();

        #pragma unroll 8
        for (int kk = 0; kk < 32; kk++) {
            int k = ks + kk;
            float g0 = GT[(ra + 0) * 33 + kk];
            float g1 = GT[(ra + 1) * 33 + kk];
            float4 b = *(const float4*)(Msh + k * 32 + cl);
            u64 b0 = pk2(b.x, b.y), b1 = pk2(b.z, b.w);
            u64 pa0 = pk2(-g0, -g0), pa1 = pk2(-g1, -g1);
            fma2(acc[0][0], pa0, b0);
            fma2(acc[0][1], pa0, b1);
            fma2(acc[1][0], pa1, b0);
            fma2(acc[1][1], pa1, b1);
        }
    }

    float* outM = out + (size_t)bh * 16384;
    #pragma unroll
    for (int i = 0; i < 2; i++)
        #pragma unroll
        for (int p = 0; p < 2; p++)
            *(u64*)(outM + (size_t)(ra + i) * 128 + cb + 2 * p) = acc[i][p];

    if (q == 0 && tid < 128) {
        float s = z[(size_t)bh * 128 + tid];
        for (int c = 0; c < ns; c++)
            #pragma unroll
            for (int j = 0; j < 8; j++)
                s += g_zs[(size_t)s_slot[c] * 1024 + j * 128 + tid];
        out[(size_t)NBH * 16384 + (size_t)bh * 128 + tid] = s;
    }
}

extern "C" void kernel_launch(void* const* d_in, const int* in_sizes, int n_in,
                              void* d_out, int out_size) {
    const float* K = (const float*)d_in[0];
    const float* V = (const float*)d_in[1];
    const float* M = (const float*)d_in[2];
    const float* z = (const float*)d_in[3];
    float* out = (float*)d_out;

    drp1_kernel<<<NCTA, 512>>>(K, V);
    drp2_kernel<<<dim3(NBH, 4), 512>>>(M, z, out);
}

// round 13
// speedup vs baseline: 1.5887x; 1.0673x over previous
#include <cuda_runtime.h>
#include <cuda_fp16.h>
#include <cstdint>

// new_M = M + phi^T V - (phi^T phi) M ; new_z = z + colsum(phi); phi = elu(K)+1
// K,V: (64, 8192, 128) fp32 flattened over (b,h) -> contiguous (524288, 128).
// Phase1: persistent balanced mapping: 148 CTAs, each owns ~110 global
//   32-row chunks (chunk ch -> bh = ch>>8). Fused fp16 mma.sync CTA:
//   warps 0-7 G = phi^T phi (symmetric band tiling), warps 8-15 A = phi^T V.
//   On bh-boundary / end, flush partial G/A/z to per-(cta,seg) scratch.
// Phase2: per bh, enumerate contributing (cta,seg) slots (pad to 4 with the
//   permanently-zero slot 1), fixed-unrolled reduce, new_M = M + A - G*M.

#define NBH 64
#define NCTA 148
#define TOTCH 16384          // 64 bh * 256 chunks of 32 rows

__device__ float g_Gs[(size_t)NCTA * 2 * 16384];
__device__ float g_As[(size_t)NCTA * 2 * 16384];
__device__ float g_zs[(size_t)NCTA * 2 * 1024];

typedef unsigned long long u64;

// ---------------- helpers ----------------
__device__ __forceinline__ uint32_t smem_u32(const void* p) {
    uint32_t a;
    asm("{ .reg .u64 t; cvta.to.shared.u64 t, %1; cvt.u32.u64 %0, t; }"
        : "=r"(a) : "l"(p));
    return a;
}
__device__ __forceinline__ void ldsm4(uint32_t* r, uint32_t a) {
    asm volatile("ldmatrix.sync.aligned.m8n8.x4.shared.b16 {%0,%1,%2,%3}, [%4];"
                 : "=r"(r[0]), "=r"(r[1]), "=r"(r[2]), "=r"(r[3]) : "r"(a));
}
__device__ __forceinline__ void mma16816(float* c, const uint32_t* a,
                                         uint32_t b0, uint32_t b1) {
    asm volatile(
        "mma.sync.aligned.m16n8k16.row.col.f32.f16.f16.f32 "
        "{%0,%1,%2,%3}, {%4,%5,%6,%7}, {%8,%9}, {%0,%1,%2,%3};"
        : "+f"(c[0]), "+f"(c[1]), "+f"(c[2]), "+f"(c[3])
        : "r"(a[0]), "r"(a[1]), "r"(a[2]), "r"(a[3]), "r"(b0), "r"(b1));
}
__device__ __forceinline__ float phi_f(float x) {
    return x > 0.f ? x + 1.f : __expf(x);
}
__device__ __forceinline__ uint32_t packh2(float s1, float s0) {
    uint32_t r;  // low half <- s0, high half <- s1
    asm("cvt.rn.f16x2.f32 %0, %1, %2;" : "=r"(r) : "f"(s1), "f"(s0));
    return r;
}
// u32 index in an 8KB [d(128)][sq(16)] tile, XOR-swizzled on 16B groups
__device__ __forceinline__ int stoff(int d, int sq) {
    return (d << 4) + ((((sq >> 2) ^ ((d >> 1) & 3))) << 2) + (sq & 3);
}
// byte address for a 16B row-fragment: row d, 16B-group g
__device__ __forceinline__ uint32_t frag_addr(uint32_t base, int d, int g) {
    return base + (d << 6) + (((g ^ ((d >> 1) & 3))) << 4);
}

// ---------------------------------------------------------------------------
// Phase 1. grid NCTA, 512 threads, persistent balanced chunks.
// ---------------------------------------------------------------------------
__global__ __launch_bounds__(512, 1)
void drp1_kernel(const float* __restrict__ K, const float* __restrict__ V) {
    __shared__ uint32_t smA[2][2048];   // phi fp16x2 [d][sq] swizzled
    __shared__ uint32_t smB[2][2048];   // V   fp16x2 [d][sq] swizzled

    const int cta = blockIdx.x;
    const int start = (cta * TOTCH) / NCTA;
    const int end   = ((cta + 1) * TOTCH) / NCTA;

    const int tid = threadIdx.x, w = tid >> 5, l = tid & 31;
    const int tg = w >> 3, w8 = w & 7;
    const int mb = (w8 & 1) * 64, nb = (w8 >> 1) * 32;      // A warps
    const int band = (w8 < 4) ? w8 : 11 - w8;               // G warps
    const int rbase = band * 16, ntlo = 2 * band;
    const int d2 = tid & 63;          // d-pair owner (staging)
    const int sq0 = tid >> 6;         // 0..7
    const int r = l >> 2, cc = 2 * (l & 3);

    const uint32_t baseA0 = smem_u32(smA), baseB0 = smem_u32(smB);

    float accs[16][4];
    #pragma unroll
    for (int i = 0; i < 16; i++)
        #pragma unroll
        for (int qq = 0; qq < 4; qq++) accs[i][qq] = 0.f;
    float z0 = 0.f, z1 = 0.f;
    int seg = 0;
    int b1 = ((start >> 8) + 1) << 8;   // next bh boundary chunk

    float2 kp[4], vp[4];

    // ---- prologue: load + convert chunk `start` into buf 0 ----
    {
        const float* Kc = K + (size_t)start * 4096;
        const float* Vc = V + (size_t)start * 4096;
        #pragma unroll
        for (int j = 0; j < 2; j++) {
            const float* kr = Kc + (size_t)((sq0 + 8 * j) << 1) * 128 + 2 * d2;
            const float* vr = Vc + (size_t)((sq0 + 8 * j) << 1) * 128 + 2 * d2;
            kp[2 * j] = __ldg((const float2*)kr);
            kp[2 * j + 1] = __ldg((const float2*)(kr + 128));
            vp[2 * j] = __ldg((const float2*)vr);
            vp[2 * j + 1] = __ldg((const float2*)(vr + 128));
        }
        #pragma unroll
        for (int j = 0; j < 2; j++) {
            const int sq = sq0 + 8 * j;
            float p00 = phi_f(kp[2 * j].x),     p01 = phi_f(kp[2 * j].y);
            float p10 = phi_f(kp[2 * j + 1].x), p11 = phi_f(kp[2 * j + 1].y);
            smA[0][stoff(2 * d2, sq)]     = packh2(p10, p00);
            smA[0][stoff(2 * d2 + 1, sq)] = packh2(p11, p01);
            z0 += p00 + p10;
            z1 += p01 + p11;
            smB[0][stoff(2 * d2, sq)]     = packh2(vp[2 * j + 1].x, vp[2 * j].x);
            smB[0][stoff(2 * d2 + 1, sq)] = packh2(vp[2 * j + 1].y, vp[2 * j].y);
        }
    }
    __syncthreads();

    for (int ch = start; ch < end; ch++) {
        const int buf = (ch - start) & 1, nbuf = buf ^ 1;
        const bool has_next = (ch + 1 < end);

        // ---- prefetch chunk ch+1 ----
        if (has_next) {
            const float* Kc = K + (size_t)(ch + 1) * 4096;
            const float* Vc = V + (size_t)(ch + 1) * 4096;
            #pragma unroll
            for (int j = 0; j < 2; j++) {
                const float* kr = Kc + (size_t)((sq0 + 8 * j) << 1) * 128 + 2 * d2;
                const float* vr = Vc + (size_t)((sq0 + 8 * j) << 1) * 128 + 2 * d2;
                kp[2 * j] = __ldg((const float2*)kr);
                kp[2 * j + 1] = __ldg((const float2*)(kr + 128));
                vp[2 * j] = __ldg((const float2*)vr);
                vp[2 * j + 1] = __ldg((const float2*)(vr + 128));
            }
        }

        // ---- mma on buf ----
        {
            const uint32_t bA = baseA0 + (uint32_t)buf * 8192;
            if (tg == 0) {
                // G band warp: rows [rbase,rbase+16), cols [16*band,128)
                #pragma unroll
                for (int ks = 0; ks < 2; ks++) {
                    const int g = 2 * ks + (l >> 4);
                    uint32_t af[4];
                    ldsm4(af, frag_addr(bA, rbase + (l & 15), g));
                    #pragma unroll
                    for (int p = 0; p < 8; p++) {
                        if (p >= band) {
                            uint32_t bb[4];
                            ldsm4(bb, frag_addr(bA, 16 * p + (l & 15), g));
                            mma16816(accs[2 * p],     af, bb[0], bb[2]);
                            mma16816(accs[2 * p + 1], af, bb[1], bb[3]);
                        }
                    }
                }
            } else {
                // A warp: 64x32 tile
                const uint32_t bOp = baseB0 + (uint32_t)buf * 8192;
                #pragma unroll
                for (int ks = 0; ks < 2; ks++) {
                    const int g = 2 * ks + (l >> 4);
                    uint32_t af[4][4];
                    #pragma unroll
                    for (int mt = 0; mt < 4; mt++)
                        ldsm4(af[mt], frag_addr(bA, mb + 16 * mt + (l & 15), g));
                    uint32_t bb[2][4];
                    #pragma unroll
                    for (int p = 0; p < 2; p++)
                        ldsm4(bb[p], frag_addr(bOp, nb + 16 * p + (l & 15), g));
                    #pragma unroll
                    for (int mt = 0; mt < 4; mt++)
                        #pragma unroll
                        for (int nt = 0; nt < 4; nt++)
                            mma16816(accs[mt * 4 + nt], af[mt],
                                     bb[nt >> 1][nt & 1], bb[nt >> 1][2 + (nt & 1)]);
                }
            }
        }

        // ---- segment flush (bh boundary or end of range) ----
        if (ch + 1 == b1 || ch + 1 == end) {
            const int slot = cta * 2 + seg;
            if (tg == 0) {
                float* dst = g_Gs + (size_t)slot * 16384;
                const int row0 = rbase + r, row1 = rbase + r + 8;
                #pragma unroll
                for (int nt = 0; nt < 16; nt++) {
                    if (nt >= ntlo) {
                        const int col = 8 * nt + cc;
                        *(float2*)(dst + (size_t)row0 * 128 + col) =
                            make_float2(accs[nt][0], accs[nt][1]);
                        *(float2*)(dst + (size_t)row1 * 128 + col) =
                            make_float2(accs[nt][2], accs[nt][3]);
                        if (nt >= ntlo + 2) {   // mirror strict-upper into lower
                            dst[(size_t)col * 128 + row0]       = accs[nt][0];
                            dst[(size_t)(col + 1) * 128 + row0] = accs[nt][1];
                            dst[(size_t)col * 128 + row1]       = accs[nt][2];
                            dst[(size_t)(col + 1) * 128 + row1] = accs[nt][3];
                        }
                    }
                }
            } else {
                float* dst = g_As + (size_t)slot * 16384;
                #pragma unroll
                for (int mt = 0; mt < 4; mt++)
                    #pragma unroll
                    for (int nt = 0; nt < 4; nt++) {
                        int row = mb + 16 * mt + r, col = nb + 8 * nt + cc;
                        *(float2*)(dst + (size_t)row * 128 + col) =
                            make_float2(accs[mt * 4 + nt][0], accs[mt * 4 + nt][1]);
                        *(float2*)(dst + (size_t)(row + 8) * 128 + col) =
                            make_float2(accs[mt * 4 + nt][2], accs[mt * 4 + nt][3]);
                    }
            }
            // z (all 512 threads own unique (sq0, d2) slots)
            *(float2*)(g_zs + (size_t)slot * 1024 + sq0 * 128 + 2 * d2) =
                make_float2(z0, z1);

            seg = 1; b1 = 1 << 30;
            #pragma unroll
            for (int i = 0; i < 16; i++)
                #pragma unroll
                for (int qq = 0; qq < 4; qq++) accs[i][qq] = 0.f;
            z0 = z1 = 0.f;
        }

        // ---- convert + store chunk ch+1 into nbuf ----
        if (has_next) {
            #pragma unroll
            for (int j = 0; j < 2; j++) {
                const int sq = sq0 + 8 * j;
                float p00 = phi_f(kp[2 * j].x),     p01 = phi_f(kp[2 * j].y);
                float p10 = phi_f(kp[2 * j + 1].x), p11 = phi_f(kp[2 * j + 1].y);
                smA[nbuf][stoff(2 * d2, sq)]     = packh2(p10, p00);
                smA[nbuf][stoff(2 * d2 + 1, sq)] = packh2(p11, p01);
                z0 += p00 + p10;
                z1 += p01 + p11;
                smB[nbuf][stoff(2 * d2, sq)]     = packh2(vp[2 * j + 1].x, vp[2 * j].x);
                smB[nbuf][stoff(2 * d2 + 1, sq)] = packh2(vp[2 * j + 1].y, vp[2 * j].y);
            }
        }
        __syncthreads();
    }
}

// ---------------------------------------------------------------------------
// Phase 2: new_M = M + A - G*M ; new_z. grid (64, 4), 512 threads.
// Fixed 4-slot reduction (pad with permanently-zero slot 1).
// ---------------------------------------------------------------------------
__device__ __forceinline__ u64 pk2(float x, float y) {
    u64 r; asm("mov.b64 %0,{%1,%2};" : "=l"(r) : "f"(x), "f"(y)); return r;
}
__device__ __forceinline__ void fma2(u64& c, u64 a, u64 b) {
    asm("fma.rn.f32x2 %0,%1,%2,%0;" : "+l"(c) : "l"(a), "l"(b));
}
__device__ __forceinline__ void add2(u64& c, u64 a) {
    asm("add.rn.f32x2 %0,%1,%0;" : "+l"(c) : "l"(a));
}

__global__ __launch_bounds__(512, 2)
void drp2_kernel(const float* __restrict__ M, const float* __restrict__ z,
                 float* __restrict__ out) {
    const int bh = blockIdx.x, q = blockIdx.y;
    __shared__ float GT[128 * 33];    // GT[i][kk], pad 33
    __shared__ float Msh[128 * 32];   // M[:, q*32 : q*32+32]
    __shared__ int s_slot[4];

    const int tid = threadIdx.x;
    const int tx = tid & 7, ty = tid >> 3;    // 8 col-groups x 64 row-groups
    const int ra = ty * 2;                    // 2 rows
    const int cl = tx * 4;                    // local col (0..28)
    const int cb = q * 32 + cl;               // global col

    const float* Mp = M + (size_t)bh * 16384;

    // enumerate contributing (cta, seg) scratch slots; pad to 4 with slot 1
    // (cta 0 never crosses a bh boundary -> slot 1 is never written -> all-zero)
    if (tid == 0) {
        const int lo = bh << 8, hi = lo + 256;
        int cnt = 0;
        int i0 = (lo * NCTA) / TOTCH;
        if (i0 > 0) i0--;
        for (int i = i0; i < NCTA && cnt < 4; i++) {
            int s = (i * TOTCH) / NCTA;
            if (s >= hi) break;
            int e = ((i + 1) * TOTCH) / NCTA;
            if (e > lo) {
                int sg = ((s >> 8) == bh) ? 0 : 1;
                s_slot[cnt++] = i * 2 + sg;
            }
        }
        while (cnt < 4) s_slot[cnt++] = 1;   // zero pad slot
    }

    // stage M slice
    for (int e = tid; e < 1024; e += 512) {
        int row = e >> 3, c4 = (e & 7) * 4;
        *(float4*)(Msh + row * 32 + c4) =
            __ldg((const float4*)(Mp + (size_t)row * 128 + q * 32 + c4));
    }
    __syncthreads();

    // register-resident slot base pointers
    const float* Ap[4];
    const float* Gp[4];
    const float* Zp[4];
    #pragma unroll
    for (int s = 0; s < 4; s++) {
        const int sl = s_slot[s];
        Ap[s] = g_As + (size_t)sl * 16384;
        Gp[s] = g_Gs + (size_t)sl * 16384;
        Zp[s] = g_zs + (size_t)sl * 1024;
    }

    u64 acc[2][2];
    #pragma unroll
    for (int i = 0; i < 2; i++) {
        #pragma unroll
        for (int p = 0; p < 2; p++) {
            size_t o = (size_t)(ra + i) * 128 + cb + 2 * p;
            float2 m = *(const float2*)(Msh + (ra + i) * 32 + cl + 2 * p);
            u64 a = pk2(m.x, m.y);
            #pragma unroll
            for (int s = 0; s < 4; s++)
                add2(a, *(const u64*)(Ap[s] + o));
            acc[i][p] = a;
        }
    }

    for (int ks = 0; ks < 128; ks += 32) {
        __syncthreads();
        for (int e = tid; e < 128 * 32; e += 512) {
            int kk = e & 31, i = e >> 5;
            size_t o = (size_t)i * 128 + ks + kk;
            float s = 0.f;
            #pragma unroll
            for (int c = 0; c < 4; c++)
                s += Gp[c][o];
            GT[i * 33 + kk] = s;
        }
        __syncthreads();

        #pragma unroll 8
        for (int kk = 0; kk < 32; kk++) {
            int k = ks + kk;
            float g0 = GT[(ra + 0) * 33 + kk];
            float g1 = GT[(ra + 1) * 33 + kk];
            float4 b = *(const float4*)(Msh + k * 32 + cl);
            u64 b0 = pk2(b.x, b.y), b1 = pk2(b.z, b.w);
            u64 pa0 = pk2(-g0, -g0), pa1 = pk2(-g1, -g1);
            fma2(acc[0][0], pa0, b0);
            fma2(acc[0][1], pa0, b1);
            fma2(acc[1][0], pa1, b0);
            fma2(acc[1][1], pa1, b1);
        }
    }

    float* outM = out + (size_t)bh * 16384;
    #pragma unroll
    for (int i = 0; i < 2; i++)
        #pragma unroll
        for (int p = 0; p < 2; p++)
            *(u64*)(outM + (size_t)(ra + i) * 128 + cb + 2 * p) = acc[i][p];

    if (q == 0 && tid < 128) {
        float s = z[(size_t)bh * 128 + tid];
        #pragma unroll
        for (int c = 0; c < 4; c++)
            #pragma unroll
            for (int j = 0; j < 8; j++)
                s += Zp[c][j * 128 + tid];
        out[(size_t)NBH * 16384 + (size_t)bh * 128 + tid] = s;
    }
}

extern "C" void kernel_launch(void* const* d_in, const int* in_sizes, int n_in,
                              void* d_out, int out_size) {
    const float* K = (const float*)d_in[0];
    const float* V = (const float*)d_in[1];
    const float* M = (const float*)d_in[2];
    const float* z = (const float*)d_in[3];
    float* out = (float*)d_out;

    drp1_kernel<<<NCTA, 512>>>(K, V);
    drp2_kernel<<<dim3(NBH, 4), 512>>>(M, z, out);
}

// round 14
// speedup vs baseline: 1.6193x; 1.0193x over previous
#include <cuda_runtime.h>
#include <cuda_fp16.h>
#include <cstdint>

// new_M = M + phi^T V - (phi^T phi) M ; new_z = z + colsum(phi); phi = elu(K)+1
// K,V: (64, 8192, 128) fp32 flattened over (b,h) -> contiguous (524288, 128).
// Phase0: zero per-bh accumulators (4.2 MB, L2-resident).
// Phase1: persistent balanced mapping: 148 CTAs x ~110 32-row chunks.
//   Fused fp16 mma.sync: warps 0-7 G = phi^T phi (symmetric band tiling),
//   warps 8-15 A = phi^T V. Segment flush = atomicAdd into per-bh G/A/z.
// Phase2: single-source (L2-hot) new_M = M + A - G*M, new_z.

#define NBH 64
#define NCTA 148
#define TOTCH 16384          // 64 bh * 256 chunks of 32 rows

__device__ float g_G[(size_t)NBH * 16384];
__device__ float g_A[(size_t)NBH * 16384];
__device__ float g_z[(size_t)NBH * 128];

typedef unsigned long long u64;

// ---------------- helpers ----------------
__device__ __forceinline__ uint32_t smem_u32(const void* p) {
    uint32_t a;
    asm("{ .reg .u64 t; cvta.to.shared.u64 t, %1; cvt.u32.u64 %0, t; }"
        : "=r"(a) : "l"(p));
    return a;
}
__device__ __forceinline__ void ldsm4(uint32_t* r, uint32_t a) {
    asm volatile("ldmatrix.sync.aligned.m8n8.x4.shared.b16 {%0,%1,%2,%3}, [%4];"
                 : "=r"(r[0]), "=r"(r[1]), "=r"(r[2]), "=r"(r[3]) : "r"(a));
}
__device__ __forceinline__ void mma16816(float* c, const uint32_t* a,
                                         uint32_t b0, uint32_t b1) {
    asm volatile(
        "mma.sync.aligned.m16n8k16.row.col.f32.f16.f16.f32 "
        "{%0,%1,%2,%3}, {%4,%5,%6,%7}, {%8,%9}, {%0,%1,%2,%3};"
        : "+f"(c[0]), "+f"(c[1]), "+f"(c[2]), "+f"(c[3])
        : "r"(a[0]), "r"(a[1]), "r"(a[2]), "r"(a[3]), "r"(b0), "r"(b1));
}
__device__ __forceinline__ float phi_f(float x) {
    return x > 0.f ? x + 1.f : __expf(x);
}
__device__ __forceinline__ uint32_t packh2(float s1, float s0) {
    uint32_t r;  // low half <- s0, high half <- s1
    asm("cvt.rn.f16x2.f32 %0, %1, %2;" : "=r"(r) : "f"(s1), "f"(s0));
    return r;
}
// u32 index in an 8KB [d(128)][sq(16)] tile, XOR-swizzled on 16B groups
__device__ __forceinline__ int stoff(int d, int sq) {
    return (d << 4) + ((((sq >> 2) ^ ((d >> 1) & 3))) << 2) + (sq & 3);
}
// byte address for a 16B row-fragment: row d, 16B-group g
__device__ __forceinline__ uint32_t frag_addr(uint32_t base, int d, int g) {
    return base + (d << 6) + (((g ^ ((d >> 1) & 3))) << 4);
}

// ---------------------------------------------------------------------------
// Phase 0: zero accumulators. 526336 float4 total.
// ---------------------------------------------------------------------------
__global__ __launch_bounds__(512, 4)
void drp0_kernel() {
    const int i = blockIdx.x * 512 + threadIdx.x;   // grid 514 * 512 = 263168
    // g_G: 262144 f4, g_A: 262144 f4, g_z: 2048 f4
    if (i < 262144) {
        *(float4*)(g_G + (size_t)i * 4) = make_float4(0.f, 0.f, 0.f, 0.f);
        *(float4*)(g_A + (size_t)i * 4) = make_float4(0.f, 0.f, 0.f, 0.f);
    }
    if (i < 2048)
        *(float4*)(g_z + (size_t)i * 4) = make_float4(0.f, 0.f, 0.f, 0.f);
}

// ---------------------------------------------------------------------------
// Phase 1. grid NCTA, 512 threads, persistent balanced chunks.
// ---------------------------------------------------------------------------
__global__ __launch_bounds__(512, 1)
void drp1_kernel(const float* __restrict__ K, const float* __restrict__ V) {
    __shared__ uint32_t smA[2][2048];   // phi fp16x2 [d][sq] swizzled
    __shared__ uint32_t smB[2][2048];   // V   fp16x2 [d][sq] swizzled

    const int cta = blockIdx.x;
    const int start = (cta * TOTCH) / NCTA;
    const int end   = ((cta + 1) * TOTCH) / NCTA;

    const int tid = threadIdx.x, w = tid >> 5, l = tid & 31;
    const int tg = w >> 3, w8 = w & 7;
    const int mb = (w8 & 1) * 64, nb = (w8 >> 1) * 32;      // A warps
    const int band = (w8 < 4) ? w8 : 11 - w8;               // G warps
    const int rbase = band * 16, ntlo = 2 * band;
    const int d2 = tid & 63;          // d-pair owner (staging)
    const int sq0 = tid >> 6;         // 0..7
    const int r = l >> 2, cc = 2 * (l & 3);

    const uint32_t baseA0 = smem_u32(smA), baseB0 = smem_u32(smB);

    float accs[16][4];
    #pragma unroll
    for (int i = 0; i < 16; i++)
        #pragma unroll
        for (int qq = 0; qq < 4; qq++) accs[i][qq] = 0.f;
    float z0 = 0.f, z1 = 0.f;
    int b1 = ((start >> 8) + 1) << 8;   // next bh boundary chunk

    float2 kp[4], vp[4];

    // ---- prologue: load + convert chunk `start` into buf 0 ----
    {
        const float* Kc = K + (size_t)start * 4096;
        const float* Vc = V + (size_t)start * 4096;
        #pragma unroll
        for (int j = 0; j < 2; j++) {
            const float* kr = Kc + (size_t)((sq0 + 8 * j) << 1) * 128 + 2 * d2;
            const float* vr = Vc + (size_t)((sq0 + 8 * j) << 1) * 128 + 2 * d2;
            kp[2 * j] = __ldg((const float2*)kr);
            kp[2 * j + 1] = __ldg((const float2*)(kr + 128));
            vp[2 * j] = __ldg((const float2*)vr);
            vp[2 * j + 1] = __ldg((const float2*)(vr + 128));
        }
        #pragma unroll
        for (int j = 0; j < 2; j++) {
            const int sq = sq0 + 8 * j;
            float p00 = phi_f(kp[2 * j].x),     p01 = phi_f(kp[2 * j].y);
            float p10 = phi_f(kp[2 * j + 1].x), p11 = phi_f(kp[2 * j + 1].y);
            smA[0][stoff(2 * d2, sq)]     = packh2(p10, p00);
            smA[0][stoff(2 * d2 + 1, sq)] = packh2(p11, p01);
            z0 += p00 + p10;
            z1 += p01 + p11;
            smB[0][stoff(2 * d2, sq)]     = packh2(vp[2 * j + 1].x, vp[2 * j].x);
            smB[0][stoff(2 * d2 + 1, sq)] = packh2(vp[2 * j + 1].y, vp[2 * j].y);
        }
    }
    __syncthreads();

    for (int ch = start; ch < end; ch++) {
        const int buf = (ch - start) & 1, nbuf = buf ^ 1;
        const bool has_next = (ch + 1 < end);

        // ---- prefetch chunk ch+1 ----
        if (has_next) {
            const float* Kc = K + (size_t)(ch + 1) * 4096;
            const float* Vc = V + (size_t)(ch + 1) * 4096;
            #pragma unroll
            for (int j = 0; j < 2; j++) {
                const float* kr = Kc + (size_t)((sq0 + 8 * j) << 1) * 128 + 2 * d2;
                const float* vr = Vc + (size_t)((sq0 + 8 * j) << 1) * 128 + 2 * d2;
                kp[2 * j] = __ldg((const float2*)kr);
                kp[2 * j + 1] = __ldg((const float2*)(kr + 128));
                vp[2 * j] = __ldg((const float2*)vr);
                vp[2 * j + 1] = __ldg((const float2*)(vr + 128));
            }
        }

        // ---- mma on buf ----
        {
            const uint32_t bA = baseA0 + (uint32_t)buf * 8192;
            if (tg == 0) {
                // G band warp: rows [rbase,rbase+16), cols [16*band,128)
                #pragma unroll
                for (int ks = 0; ks < 2; ks++) {
                    const int g = 2 * ks + (l >> 4);
                    uint32_t af[4];
                    ldsm4(af, frag_addr(bA, rbase + (l & 15), g));
                    #pragma unroll
                    for (int p = 0; p < 8; p++) {
                        if (p >= band) {
                            uint32_t bb[4];
                            ldsm4(bb, frag_addr(bA, 16 * p + (l & 15), g));
                            mma16816(accs[2 * p],     af, bb[0], bb[2]);
                            mma16816(accs[2 * p + 1], af, bb[1], bb[3]);
                        }
                    }
                }
            } else {
                // A warp: 64x32 tile
                const uint32_t bOp = baseB0 + (uint32_t)buf * 8192;
                #pragma unroll
                for (int ks = 0; ks < 2; ks++) {
                    const int g = 2 * ks + (l >> 4);
                    uint32_t af[4][4];
                    #pragma unroll
                    for (int mt = 0; mt < 4; mt++)
                        ldsm4(af[mt], frag_addr(bA, mb + 16 * mt + (l & 15), g));
                    uint32_t bb[2][4];
                    #pragma unroll
                    for (int p = 0; p < 2; p++)
                        ldsm4(bb[p], frag_addr(bOp, nb + 16 * p + (l & 15), g));
                    #pragma unroll
                    for (int mt = 0; mt < 4; mt++)
                        #pragma unroll
                        for (int nt = 0; nt < 4; nt++)
                            mma16816(accs[mt * 4 + nt], af[mt],
                                     bb[nt >> 1][nt & 1], bb[nt >> 1][2 + (nt & 1)]);
                }
            }
        }

        // ---- segment flush (bh boundary or end of range): atomicAdd ----
        if (ch + 1 == b1 || ch + 1 == end) {
            const int fbh = ch >> 8;
            if (tg == 0) {
                float* dst = g_G + (size_t)fbh * 16384;
                const int row0 = rbase + r, row1 = rbase + r + 8;
                #pragma unroll
                for (int nt = 0; nt < 16; nt++) {
                    if (nt >= ntlo) {
                        const int col = 8 * nt + cc;
                        atomicAdd(dst + (size_t)row0 * 128 + col,     accs[nt][0]);
                        atomicAdd(dst + (size_t)row0 * 128 + col + 1, accs[nt][1]);
                        atomicAdd(dst + (size_t)row1 * 128 + col,     accs[nt][2]);
                        atomicAdd(dst + (size_t)row1 * 128 + col + 1, accs[nt][3]);
                        if (nt >= ntlo + 2) {   // mirror strict-upper into lower
                            atomicAdd(dst + (size_t)col * 128 + row0,       accs[nt][0]);
                            atomicAdd(dst + (size_t)(col + 1) * 128 + row0, accs[nt][1]);
                            atomicAdd(dst + (size_t)col * 128 + row1,       accs[nt][2]);
                            atomicAdd(dst + (size_t)(col + 1) * 128 + row1, accs[nt][3]);
                        }
                    }
                }
            } else {
                float* dst = g_A + (size_t)fbh * 16384;
                #pragma unroll
                for (int mt = 0; mt < 4; mt++)
                    #pragma unroll
                    for (int nt = 0; nt < 4; nt++) {
                        int row = mb + 16 * mt + r, col = nb + 8 * nt + cc;
                        atomicAdd(dst + (size_t)row * 128 + col,       accs[mt * 4 + nt][0]);
                        atomicAdd(dst + (size_t)row * 128 + col + 1,   accs[mt * 4 + nt][1]);
                        atomicAdd(dst + (size_t)(row + 8) * 128 + col,     accs[mt * 4 + nt][2]);
                        atomicAdd(dst + (size_t)(row + 8) * 128 + col + 1, accs[mt * 4 + nt][3]);
                    }
            }
            // z: 8 threads (sq0 groups) collide per d — atomic handles it
            atomicAdd(g_z + (size_t)fbh * 128 + 2 * d2,     z0);
            atomicAdd(g_z + (size_t)fbh * 128 + 2 * d2 + 1, z1);

            b1 = 1 << 30;
            #pragma unroll
            for (int i = 0; i < 16; i++)
                #pragma unroll
                for (int qq = 0; qq < 4; qq++) accs[i][qq] = 0.f;
            z0 = z1 = 0.f;
        }

        // ---- convert + store chunk ch+1 into nbuf ----
        if (has_next) {
            #pragma unroll
            for (int j = 0; j < 2; j++) {
                const int sq = sq0 + 8 * j;
                float p00 = phi_f(kp[2 * j].x),     p01 = phi_f(kp[2 * j].y);
                float p10 = phi_f(kp[2 * j + 1].x), p11 = phi_f(kp[2 * j + 1].y);
                smA[nbuf][stoff(2 * d2, sq)]     = packh2(p10, p00);
                smA[nbuf][stoff(2 * d2 + 1, sq)] = packh2(p11, p01);
                z0 += p00 + p10;
                z1 += p01 + p11;
                smB[nbuf][stoff(2 * d2, sq)]     = packh2(vp[2 * j + 1].x, vp[2 * j].x);
                smB[nbuf][stoff(2 * d2 + 1, sq)] = packh2(vp[2 * j + 1].y, vp[2 * j].y);
            }
        }
        __syncthreads();
    }
}

// ---------------------------------------------------------------------------
// Phase 2: new_M = M + A - G*M ; new_z. grid (64, 4), 512 threads.
// Single L2-hot source per bh.
// ---------------------------------------------------------------------------
__device__ __forceinline__ u64 pk2(float x, float y) {
    u64 r; asm("mov.b64 %0,{%1,%2};" : "=l"(r) : "f"(x), "f"(y)); return r;
}
__device__ __forceinline__ void fma2(u64& c, u64 a, u64 b) {
    asm("fma.rn.f32x2 %0,%1,%2,%0;" : "+l"(c) : "l"(a), "l"(b));
}
__device__ __forceinline__ void add2(u64& c, u64 a) {
    asm("add.rn.f32x2 %0,%1,%0;" : "+l"(c) : "l"(a));
}

__global__ __launch_bounds__(512, 2)
void drp2_kernel(const float* __restrict__ M, const float* __restrict__ z,
                 float* __restrict__ out) {
    const int bh = blockIdx.x, q = blockIdx.y;
    __shared__ float GT[128 * 33];    // GT[i][kk], pad 33
    __shared__ float Msh[128 * 32];   // M[:, q*32 : q*32+32]

    const int tid = threadIdx.x;
    const int tx = tid & 7, ty = tid >> 3;    // 8 col-groups x 64 row-groups
    const int ra = ty * 2;                    // 2 rows
    const int cl = tx * 4;                    // local col (0..28)
    const int cb = q * 32 + cl;               // global col

    const float* Mp = M + (size_t)bh * 16384;
    const float* Ap = g_A + (size_t)bh * 16384;
    const float* Gp = g_G + (size_t)bh * 16384;

    // stage M slice
    for (int e = tid; e < 1024; e += 512) {
        int row = e >> 3, c4 = (e & 7) * 4;
        *(float4*)(Msh + row * 32 + c4) =
            __ldg((const float4*)(Mp + (size_t)row * 128 + q * 32 + c4));
    }
    __syncthreads();

    u64 acc[2][2];
    #pragma unroll
    for (int i = 0; i < 2; i++) {
        #pragma unroll
        for (int p = 0; p < 2; p++) {
            size_t o = (size_t)(ra + i) * 128 + cb + 2 * p;
            float2 m = *(const float2*)(Msh + (ra + i) * 32 + cl + 2 * p);
            u64 a = pk2(m.x, m.y);
            add2(a, *(const u64*)(Ap + o));
            acc[i][p] = a;
        }
    }

    for (int ks = 0; ks < 128; ks += 32) {
        __syncthreads();
        for (int e = tid; e < 128 * 32; e += 512) {
            int kk = e & 31, i = e >> 5;
            GT[i * 33 + kk] = Gp[(size_t)i * 128 + ks + kk];
        }
        __syncthreads();

        #pragma unroll 8
        for (int kk = 0; kk < 32; kk++) {
            int k = ks + kk;
            float g0 = GT[(ra + 0) * 33 + kk];
            float g1 = GT[(ra + 1) * 33 + kk];
            float4 b = *(const float4*)(Msh + k * 32 + cl);
            u64 b0 = pk2(b.x, b.y), b1 = pk2(b.z, b.w);
            u64 pa0 = pk2(-g0, -g0), pa1 = pk2(-g1, -g1);
            fma2(acc[0][0], pa0, b0);
            fma2(acc[0][1], pa0, b1);
            fma2(acc[1][0], pa1, b0);
            fma2(acc[1][1], pa1, b1);
        }
    }

    float* outM = out + (size_t)bh * 16384;
    #pragma unroll
    for (int i = 0; i < 2; i++)
        #pragma unroll
        for (int p = 0; p < 2; p++)
            *(u64*)(outM + (size_t)(ra + i) * 128 + cb + 2 * p) = acc[i][p];

    if (q == 0 && tid < 128) {
        out[(size_t)NBH * 16384 + (size_t)bh * 128 + tid] =
            z[(size_t)bh * 128 + tid] + g_z[(size_t)bh * 128 + tid];
    }
}

extern "C" void kernel_launch(void* const* d_in, const int* in_sizes, int n_in,
                              void* d_out, int out_size) {
    const float* K = (const float*)d_in[0];
    const float* V = (const float*)d_in[1];
    const float* M = (const float*)d_in[2];
    const float* z = (const float*)d_in[3];
    float* out = (float*)d_out;

    drp0_kernel<<<514, 512>>>();
    drp1_kernel<<<NCTA, 512>>>(K, V);
    drp2_kernel<<<dim3(NBH, 4), 512>>>(M, z, out);
}